// round 16
// baseline (speedup 1.0000x reference)
#include <cuda_runtime.h>
#include <cuda_bf16.h>
#include <math.h>
#include <stddef.h>
#include <stdint.h>

#define NR 2048
#define DD 2048
#define NCLS 9
#define NBB 36

// ---- scratch (device globals: allocation-free rule) ----
__device__ float g_A[NR * DD];                 // feat / x3 (fp32, residual)
__device__ float g_B[NR * DD];                 // x2 (fp32, residual)
__device__ float g_T[NR * DD];                 // mat@x fp32; cos partial S0; head partials
__device__ float g_S[NR * NR];                 // cos partial S1
__device__ __nv_bfloat16 g_XNb[NR * DD];       // normalized feats (bf16)
__device__ __nv_bfloat16 g_Mb[NR * NR];        // cosine matrix (bf16)
__device__ __nv_bfloat16 g_ATb[NR * DD];       // x^T (bf16)
__device__ __nv_bfloat16 g_Tb[NR * DD];        // softmax(mat@x) (bf16)
__device__ __nv_bfloat16 g_Wtb[DD * DD];       // Wt (bf16)
__device__ __nv_bfloat16 g_Wrb[DD * DD];       // Wr (bf16)

// =====================================================================
// helpers
// =====================================================================
__device__ __forceinline__ uint32_t smem_u32(const void* p) {
    uint32_t a;
    asm("{ .reg .u64 t; cvta.to.shared.u64 t, %1; cvt.u32.u64 %0, t; }"
        : "=r"(a) : "l"(p));
    return a;
}
__device__ __forceinline__ uint32_t pack2(float lo, float hi) {
    uint32_t r;
    asm("cvt.rn.bf16x2.f32 %0, %1, %2;" : "=r"(r) : "f"(hi), "f"(lo));
    return r;
}
#define CP_ASYNC16(dst, src) \
    asm volatile("cp.async.ca.shared.global [%0], [%1], 16;" :: "r"(dst), "l"(src) : "memory")
#define CP_COMMIT() asm volatile("cp.async.commit_group;" ::: "memory")
#define CP_WAIT(n)  asm volatile("cp.async.wait_group %0;" :: "n"(n) : "memory")
#define LDMATRIX_X4(r, addr)                                              \
    asm volatile("ldmatrix.sync.aligned.m8n8.x4.shared.b16 "              \
                 "{%0,%1,%2,%3}, [%4];"                                   \
                 : "=r"((r)[0]), "=r"((r)[1]), "=r"((r)[2]), "=r"((r)[3]) \
                 : "r"(addr))

__device__ __forceinline__ void mma_bf16(float* c, const uint32_t* a, const uint32_t* b) {
    asm volatile(
        "mma.sync.aligned.m16n8k16.row.col.f32.bf16.bf16.f32 "
        "{%0,%1,%2,%3}, {%4,%5,%6,%7}, {%8,%9}, {%0,%1,%2,%3};"
        : "+f"(c[0]), "+f"(c[1]), "+f"(c[2]), "+f"(c[3])
        : "r"(a[0]), "r"(a[1]), "r"(a[2]), "r"(a[3]), "r"(b[0]), "r"(b[1]));
}

// =====================================================================
// AvgPool + f2b (block-range dispatch)
// =====================================================================
__global__ void avgpool_f2b_kernel(const float* __restrict__ x, float* __restrict__ out,
                                   const float* __restrict__ Wt, const float* __restrict__ Wr,
                                   __nv_bfloat16* __restrict__ Wtb,
                                   __nv_bfloat16* __restrict__ Wrb) {
    __shared__ float s[128 * 49];
    const int b = blockIdx.x;
    if (b < 32768) {
        size_t block0 = (size_t)b * 128;
        const float4* src = reinterpret_cast<const float4*>(x + block0 * 49);
        float4* dst = reinterpret_cast<float4*>(s);
        for (int i = threadIdx.x; i < 128 * 49 / 4; i += 256) dst[i] = src[i];
        __syncthreads();
        if (threadIdx.x < 128) {
            float sum = 0.f;
            #pragma unroll
            for (int k = 0; k < 49; k++) sum += s[threadIdx.x * 49 + k];
            out[block0 + threadIdx.x] = sum * (1.f / 49.f);
        }
    } else {
        const int fb = b - 32768;
        const float* in = (fb < 2048) ? Wt : Wr;
        __nv_bfloat16* o8 = (fb < 2048) ? Wtb : Wrb;
        size_t i = ((size_t)(fb & 2047) * 256 + threadIdx.x) * 8;
        const float4 a = *(const float4*)(in + i);
        const float4 c = *(const float4*)(in + i + 4);
        uint4 o;
        o.x = pack2(a.x, a.y); o.y = pack2(a.z, a.w);
        o.z = pack2(c.x, c.y); o.w = pack2(c.z, c.w);
        *(uint4*)(o8 + i) = o;
    }
}

// =====================================================================
// Row L2-normalize -> bf16 (shuffle reduction, 1 barrier)
// =====================================================================
__global__ void normalize_kernel(const float* __restrict__ f, __nv_bfloat16* __restrict__ fn) {
    __shared__ float wsum[8];
    const int row = blockIdx.x, t = threadIdx.x;
    const int lane = t & 31, w = t >> 5;
    const float4* p = reinterpret_cast<const float4*>(f + (size_t)row * DD);
    float4 v0 = p[2 * t], v1 = p[2 * t + 1];
    float s = v0.x * v0.x + v0.y * v0.y + v0.z * v0.z + v0.w * v0.w
            + v1.x * v1.x + v1.y * v1.y + v1.z * v1.z + v1.w * v1.w;
    #pragma unroll
    for (int o = 16; o; o >>= 1) s += __shfl_xor_sync(0xffffffffu, s, o);
    if (lane == 0) wsum[w] = s;
    __syncthreads();
    s = wsum[0];
    #pragma unroll
    for (int i = 1; i < 8; i++) s += wsum[i];
    const float inv = 1.f / fmaxf(sqrtf(s), 1e-8f);
    uint4 o;
    o.x = pack2(v0.x * inv, v0.y * inv);
    o.y = pack2(v0.z * inv, v0.w * inv);
    o.z = pack2(v1.x * inv, v1.y * inv);
    o.w = pack2(v1.z * inv, v1.w * inv);
    *(uint4*)(fn + (size_t)row * DD + t * 8) = o;
}

// =====================================================================
// Row softmax: fp32 in -> bf16 out (shuffle reductions, 2 barriers)
// =====================================================================
__global__ void softmax_kernel(const float* __restrict__ in, __nv_bfloat16* __restrict__ outb) {
    __shared__ float wmax[8];
    __shared__ float wsum[8];
    const int row = blockIdx.x, t = threadIdx.x;
    const int lane = t & 31, w = t >> 5;
    const float4* p = reinterpret_cast<const float4*>(in + (size_t)row * NR);
    float4 u0 = p[2 * t], u1 = p[2 * t + 1];
    float v[8] = {u0.x, u0.y, u0.z, u0.w, u1.x, u1.y, u1.z, u1.w};
    float mx = v[0];
    #pragma unroll
    for (int i = 1; i < 8; i++) mx = fmaxf(mx, v[i]);
    #pragma unroll
    for (int o = 16; o; o >>= 1) mx = fmaxf(mx, __shfl_xor_sync(0xffffffffu, mx, o));
    if (lane == 0) wmax[w] = mx;
    __syncthreads();
    mx = wmax[0];
    #pragma unroll
    for (int i = 1; i < 8; i++) mx = fmaxf(mx, wmax[i]);

    float s = 0.f;
    #pragma unroll
    for (int i = 0; i < 8; i++) {
        v[i] = __expf(v[i] - mx);
        s += v[i];
    }
    #pragma unroll
    for (int o = 16; o; o >>= 1) s += __shfl_xor_sync(0xffffffffu, s, o);
    if (lane == 0) wsum[w] = s;
    __syncthreads();
    s = wsum[0];
    #pragma unroll
    for (int i = 1; i < 8; i++) s += wsum[i];

    const float inv = 1.f / s;
    uint4 o;
    o.x = pack2(v[0] * inv, v[1] * inv);
    o.y = pack2(v[2] * inv, v[3] * inv);
    o.z = pack2(v[4] * inv, v[5] * inv);
    o.w = pack2(v[6] * inv, v[7] * inv);
    *(uint4*)(outb + (size_t)row * NR + t * 8) = o;
}

// =====================================================================
// Cosine GEMM split-K: 128x128 tile, K split into 2 halves of 1024.
// grid = 272: tile = bx>>1, half = bx&1. fp32 partial -> S0/S1.
// =====================================================================
#define STG 16384

__device__ __forceinline__ void load_stage_sq(uint32_t sb32,
                                              const __nv_bfloat16* A, const __nv_bfloat16* B,
                                              int bm0, int bn0, int k0, int buf, int t) {
    const int ch = t & 7;
    const int r0 = t >> 3;
    const uint32_t abase = sb32 + (uint32_t)buf * (2 * STG);
    #pragma unroll
    for (int p = 0; p < 4; p++) {
        const int row = r0 + p * 32;
        uint32_t o = (uint32_t)row * 128 + ch * 16;
        uint32_t sw = o ^ ((o >> 3) & 0x70);
        CP_ASYNC16(abase + sw, A + (size_t)(bm0 + row) * DD + k0 + ch * 8);
        CP_ASYNC16(abase + STG + sw, B + (size_t)(bn0 + row) * DD + k0 + ch * 8);
    }
}

__global__ __launch_bounds__(256, 2)
void gemm_cos_sk(const __nv_bfloat16* __restrict__ XN,
                 float* __restrict__ S0, float* __restrict__ S1) {
    extern __shared__ char dynsm[];
    char* sb = (char*)(((uintptr_t)dynsm + 1023) & ~(uintptr_t)1023);
    const uint32_t sb32 = smem_u32(sb);
    const int t = threadIdx.x;
    const int lane = t & 31, wid = t >> 5;
    const int wm = (wid & 3) * 32;
    const int wn = (wid >> 2) * 64;

    const int half = blockIdx.x & 1;
    int rem = blockIdx.x >> 1, i = 0;
    while (rem >= 16 - i) { rem -= 16 - i; i++; }
    const int bm0 = i * 128;
    const int bn0 = (i + rem) * 128;
    const int kbase = half * 1024;
    float* S = half ? S1 : S0;

    float acc[2][8][4];
    #pragma unroll
    for (int a = 0; a < 2; a++)
        #pragma unroll
        for (int b = 0; b < 8; b++)
            #pragma unroll
            for (int q = 0; q < 4; q++) acc[a][b][q] = 0.f;

    load_stage_sq(sb32, XN, XN, bm0, bn0, kbase, 0, t);
    CP_COMMIT();

    const int a_row_l = lane & 15;
    const int a_kb = (lane >> 4) * 16;
    const int b_row_l = ((lane >> 4) << 3) + (lane & 7);
    const int b_kb = ((lane >> 3) & 1) * 16;

    for (int s = 0; s < 16; s++) {
        if (s < 15) {
            load_stage_sq(sb32, XN, XN, bm0, bn0, kbase + (s + 1) * 64, (s + 1) & 1, t);
            CP_COMMIT();
            CP_WAIT(1);
        } else {
            CP_WAIT(0);
        }
        __syncthreads();
        const uint32_t aB = sb32 + (uint32_t)(s & 1) * (2 * STG);
        const uint32_t bB = aB + STG;
        #pragma unroll
        for (int kk = 0; kk < 4; kk++) {
            const int kb = kk * 32;
            uint32_t af[2][4], bf[4][4];
            #pragma unroll
            for (int mt = 0; mt < 2; mt++) {
                uint32_t o = (uint32_t)(wm + mt * 16 + a_row_l) * 128 + kb + a_kb;
                LDMATRIX_X4(af[mt], aB + (o ^ ((o >> 3) & 0x70)));
            }
            #pragma unroll
            for (int nt2 = 0; nt2 < 4; nt2++) {
                uint32_t o = (uint32_t)(wn + nt2 * 16 + b_row_l) * 128 + kb + b_kb;
                LDMATRIX_X4(bf[nt2], bB + (o ^ ((o >> 3) & 0x70)));
            }
            #pragma unroll
            for (int mt = 0; mt < 2; mt++)
                #pragma unroll
                for (int nt2 = 0; nt2 < 4; nt2++) {
                    mma_bf16(acc[mt][nt2 * 2 + 0], af[mt], &bf[nt2][0]);
                    mma_bf16(acc[mt][nt2 * 2 + 1], af[mt], &bf[nt2][2]);
                }
        }
        __syncthreads();
    }

    const int g = lane >> 2;
    const int c2 = (lane & 3) * 2;
    #pragma unroll
    for (int mt = 0; mt < 2; mt++) {
        const int row0 = bm0 + wm + mt * 16 + g;
        #pragma unroll
        for (int nt = 0; nt < 8; nt++) {
            const int col0 = bn0 + wn + nt * 8 + c2;
            float2 o0 = {acc[mt][nt][0], acc[mt][nt][1]};
            float2 o1 = {acc[mt][nt][2], acc[mt][nt][3]};
            *(float2*)&S[(size_t)row0 * NR + col0] = o0;
            *(float2*)&S[(size_t)(row0 + 8) * NR + col0] = o1;
        }
    }
}

// =====================================================================
// FUSED cosred + transpose (block-range dispatch; both branches keep
// their per-block structure and share the static smem tile):
//  [0, 2176)        : cosred 32x32 sub-tile (Mb = bf16(S0+S1) + mirror)
//  [2176, +4096)    : 32x32 transpose tile Afp^T -> AT (bf16)
// =====================================================================
__global__ __launch_bounds__(256)
void cosred_trans_kernel(const float* __restrict__ S0, const float* __restrict__ S1,
                         __nv_bfloat16* __restrict__ C,
                         const float* __restrict__ Afp, __nv_bfloat16* __restrict__ AT) {
    __shared__ float tile[32][33];
    const int b = blockIdx.x;
    const int tx = threadIdx.x & 31, ty = threadIdx.x >> 5;

    if (b < 2176) {
        // ---- cosred branch ----
        const int tix = b >> 4, sub = b & 15;
        int rem = tix, i = 0;
        while (rem >= 16 - i) { rem -= 16 - i; i++; }
        const int bm0 = i * 128;
        const int bn0 = (i + rem) * 128;
        const int sr = bm0 + (sub >> 2) * 32;
        const int sc = bn0 + (sub & 3) * 32;

        #pragma unroll
        for (int j = 0; j < 32; j += 8) {
            const int r = sr + ty + j;
            const size_t idx = (size_t)r * NR + sc + tx;
            float v = S0[idx] + S1[idx];
            C[idx] = __float2bfloat16_rn(v);
            tile[ty + j][tx] = v;
        }
        if (bm0 != bn0) {
            __syncthreads();
            #pragma unroll
            for (int j = 0; j < 32; j += 8) {
                const int r = sc + ty + j;
                C[(size_t)r * NR + sr + tx] = __float2bfloat16_rn(tile[tx][ty + j]);
            }
        }
    } else {
        // ---- transpose branch ----
        const int idx = b - 2176;
        const int bx = idx & 63, by = idx >> 6;
        int x = bx * 32 + tx;
        int y = by * 32 + ty;
        #pragma unroll
        for (int j = 0; j < 32; j += 8)
            tile[ty + j][tx] = Afp[(size_t)(y + j) * DD + x];
        __syncthreads();
        x = by * 32 + tx;
        y = bx * 32 + ty;
        #pragma unroll
        for (int j = 0; j < 32; j += 8)
            AT[(size_t)(y + j) * DD + x] = __float2bfloat16_rn(tile[tx][ty + j]);
    }
}

// =====================================================================
// BIG bf16 NT GEMM: 256x128 CTA tile, 8 warps @ 64x64, BK=64, 3-stage.
// EPI: 0 plain fp32 | 2 (+bias[c]+res[r,c]) fp32.
// =====================================================================
#define BSTG 49152
#define NSTAGE 3

__device__ __forceinline__ void load_stage_big(uint32_t sb32,
                                               const __nv_bfloat16* A, const __nv_bfloat16* B,
                                               int bm0, int bn0, int k0, int buf, int t) {
    const int ch = t & 7;
    const int r0 = t >> 3;
    const uint32_t base = sb32 + (uint32_t)buf * BSTG;
    #pragma unroll
    for (int p = 0; p < 8; p++) {
        const int row = r0 + p * 32;
        uint32_t o = (uint32_t)row * 128 + ch * 16;
        CP_ASYNC16(base + (o ^ ((o >> 3) & 0x70)),
                   A + (size_t)(bm0 + row) * DD + k0 + ch * 8);
    }
    #pragma unroll
    for (int p = 0; p < 4; p++) {
        const int row = r0 + p * 32;
        uint32_t o = (uint32_t)row * 128 + ch * 16;
        CP_ASYNC16(base + 32768u + (o ^ ((o >> 3) & 0x70)),
                   B + (size_t)(bn0 + row) * DD + k0 + ch * 8);
    }
}

template <int EPI>
__global__ __launch_bounds__(256, 1)
void gemm_big(const __nv_bfloat16* __restrict__ A, const __nv_bfloat16* __restrict__ B,
              float* __restrict__ C,
              const float* __restrict__ bias,
              const float* __restrict__ res) {
    extern __shared__ char dynsm[];
    char* sb = (char*)(((uintptr_t)dynsm + 1023) & ~(uintptr_t)1023);
    const uint32_t sb32 = smem_u32(sb);

    const int t = threadIdx.x;
    const int lane = t & 31, wid = t >> 5;
    const int wm = (wid & 3) * 64;
    const int wn = (wid >> 2) * 64;
    const int bm0 = blockIdx.y * 256;
    const int bn0 = blockIdx.x * 128;

    float acc[4][8][4];
    #pragma unroll
    for (int i = 0; i < 4; i++)
        #pragma unroll
        for (int j = 0; j < 8; j++)
            #pragma unroll
            for (int q = 0; q < 4; q++) acc[i][j][q] = 0.f;

    load_stage_big(sb32, A, B, bm0, bn0, 0, 0, t);
    CP_COMMIT();
    load_stage_big(sb32, A, B, bm0, bn0, 64, 1, t);
    CP_COMMIT();

    const int a_row_l = lane & 15;
    const int a_kb = (lane >> 4) * 16;
    const int b_row_l = ((lane >> 4) << 3) + (lane & 7);
    const int b_kb = ((lane >> 3) & 1) * 16;

    int buf = 0;
    for (int s = 0; s < 32; s++) {
        if (s < 31) { CP_WAIT(1); } else { CP_WAIT(0); }
        __syncthreads();
        if (s < 30) {
            int nb = buf + 2; if (nb >= NSTAGE) nb -= NSTAGE;
            load_stage_big(sb32, A, B, bm0, bn0, (s + 2) * 64, nb, t);
            CP_COMMIT();
        }

        const uint32_t aB = sb32 + (uint32_t)buf * BSTG;
        const uint32_t bB = aB + 32768u;
        #pragma unroll
        for (int kk = 0; kk < 4; kk++) {
            const int kb = kk * 32;
            uint32_t af[4][4], bf[4][4];
            #pragma unroll
            for (int mt = 0; mt < 4; mt++) {
                uint32_t o = (uint32_t)(wm + mt * 16 + a_row_l) * 128 + kb + a_kb;
                LDMATRIX_X4(af[mt], aB + (o ^ ((o >> 3) & 0x70)));
            }
            #pragma unroll
            for (int nt2 = 0; nt2 < 4; nt2++) {
                uint32_t o = (uint32_t)(wn + nt2 * 16 + b_row_l) * 128 + kb + b_kb;
                LDMATRIX_X4(bf[nt2], bB + (o ^ ((o >> 3) & 0x70)));
            }
            #pragma unroll
            for (int mt = 0; mt < 4; mt++)
                #pragma unroll
                for (int nt2 = 0; nt2 < 4; nt2++) {
                    mma_bf16(acc[mt][nt2 * 2 + 0], af[mt], &bf[nt2][0]);
                    mma_bf16(acc[mt][nt2 * 2 + 1], af[mt], &bf[nt2][2]);
                }
        }
        if (++buf == NSTAGE) buf = 0;
    }

    const int g = lane >> 2;
    const int c2 = (lane & 3) * 2;
    #pragma unroll
    for (int mt = 0; mt < 4; mt++) {
        const int row0 = bm0 + wm + mt * 16 + g;
        #pragma unroll
        for (int nt = 0; nt < 8; nt++) {
            const int col0 = bn0 + wn + nt * 8 + c2;
            float v0 = acc[mt][nt][0], v1 = acc[mt][nt][1];
            float v2 = acc[mt][nt][2], v3 = acc[mt][nt][3];
            if (EPI == 2) {
                float b0 = bias[col0], b1 = bias[col0 + 1];
                const float2 r0 = *(const float2*)&res[(size_t)row0 * DD + col0];
                const float2 r1 = *(const float2*)&res[(size_t)(row0 + 8) * DD + col0];
                v0 += b0 + r0.x; v1 += b1 + r0.y;
                v2 += b0 + r1.x; v3 += b1 + r1.y;
            }
            float2 o0 = {v0, v1}, o1 = {v2, v3};
            *(float2*)&C[(size_t)row0 * DD + col0] = o0;
            *(float2*)&C[(size_t)(row0 + 8) * DD + col0] = o1;
        }
    }
}

// =====================================================================
// Head, split-K (k-step-4 inner loop: float4 W broadcasts)
// =====================================================================
__global__ __launch_bounds__(256)
void head_partial(const float* __restrict__ x,
                  const float* __restrict__ Wc, const float* __restrict__ Wb,
                  float* __restrict__ part) {
    __shared__ float Wsm[48 * 64];
    __shared__ float xs[32 * 65];
    const int rb = blockIdx.x, ks = blockIdx.y;
    const int t = threadIdx.x;
    const int r = t & 31, jg = t >> 5;

    float acc[6] = {0.f, 0.f, 0.f, 0.f, 0.f, 0.f};

    for (int k0 = ks * 256; k0 < ks * 256 + 256; k0 += 64) {
        for (int i = t; i < 48 * 64; i += 256) {
            int j = i >> 6, k = i & 63;
            if (j < 45) {
                const float* w = (j < NCLS) ? (Wc + (size_t)j * DD)
                                            : (Wb + (size_t)(j - NCLS) * DD);
                Wsm[i] = w[k0 + k];
            } else {
                Wsm[i] = 0.f;
            }
        }
        for (int i = t; i < 32 * 64; i += 256) {
            int rr = i >> 6, k = i & 63;
            xs[rr * 65 + k] = x[(size_t)(rb * 32 + rr) * DD + k0 + k];
        }
        __syncthreads();
        #pragma unroll 4
        for (int k = 0; k < 64; k += 4) {
            float xv0 = xs[r * 65 + k + 0];
            float xv1 = xs[r * 65 + k + 1];
            float xv2 = xs[r * 65 + k + 2];
            float xv3 = xs[r * 65 + k + 3];
            #pragma unroll
            for (int u = 0; u < 6; u++) {
                const int j = jg + 8 * u;
                const float4 w = *(const float4*)&Wsm[j * 64 + k];
                acc[u] += xv0 * w.x + xv1 * w.y + xv2 * w.z + xv3 * w.w;
            }
        }
        __syncthreads();
    }
    #pragma unroll
    for (int u = 0; u < 6; u++) {
        int j = jg + 8 * u;
        if (j < 45)
            part[((size_t)ks * NR + rb * 32 + r) * 45 + j] = acc[u];
    }
}

__global__ void head_reduce(const float* __restrict__ part,
                            const float* __restrict__ bc, const float* __restrict__ bb,
                            float* __restrict__ out) {
    int idx = blockIdx.x * 256 + threadIdx.x;
    if (idx >= NR * 45) return;
    int i = idx / 45, j = idx - i * 45;
    float s = 0.f;
    #pragma unroll
    for (int ks = 0; ks < 8; ks++) s += part[((size_t)ks * NR + i) * 45 + j];
    if (j < NCLS)
        out[(size_t)i * NCLS + j] = s + bc[j];
    else
        out[(size_t)NR * NCLS + (size_t)i * NBB + (j - NCLS)] = s + bb[j - NCLS];
}

// =====================================================================
extern "C" void kernel_launch(void* const* d_in, const int* in_sizes, int n_in,
                              void* d_out, int out_size) {
    const float* x  = (const float*)d_in[0];
    const float* Wt = (const float*)d_in[1];
    const float* bt = (const float*)d_in[2];
    const float* Wr = (const float*)d_in[3];
    const float* br = (const float*)d_in[4];
    const float* Wc = (const float*)d_in[5];
    const float* bc = (const float*)d_in[6];
    const float* Wb = (const float*)d_in[7];
    const float* bb = (const float*)d_in[8];
    float* out = (float*)d_out;

    float *A, *B, *T, *S;
    __nv_bfloat16 *XNb, *Mb, *ATb, *Tb, *Wtb, *Wrb;
    cudaGetSymbolAddress((void**)&A, g_A);
    cudaGetSymbolAddress((void**)&B, g_B);
    cudaGetSymbolAddress((void**)&T, g_T);
    cudaGetSymbolAddress((void**)&S, g_S);
    cudaGetSymbolAddress((void**)&XNb, g_XNb);
    cudaGetSymbolAddress((void**)&Mb, g_Mb);
    cudaGetSymbolAddress((void**)&ATb, g_ATb);
    cudaGetSymbolAddress((void**)&Tb, g_Tb);
    cudaGetSymbolAddress((void**)&Wtb, g_Wtb);
    cudaGetSymbolAddress((void**)&Wrb, g_Wrb);

    const int SMEM_SQ  = 4 * STG + 1024;          // 66560 B
    const int SMEM_BIG = NSTAGE * BSTG + 1024;    // 148480 B
    cudaFuncSetAttribute(gemm_cos_sk, cudaFuncAttributeMaxDynamicSharedMemorySize, SMEM_SQ);
    cudaFuncSetAttribute(gemm_big<0>, cudaFuncAttributeMaxDynamicSharedMemorySize, SMEM_BIG);
    cudaFuncSetAttribute(gemm_big<2>, cudaFuncAttributeMaxDynamicSharedMemorySize, SMEM_BIG);

    dim3 gbig(16, 8);
    const int GRT = 2176 + 4096;   // cosred sub-tiles + transpose tiles

    // avgpool + both weight converts in one launch
    avgpool_f2b_kernel<<<32768 + 4096, 256>>>(x, A, Wt, Wr, Wtb, Wrb);

    // ---- layer 1 ----
    normalize_kernel<<<NR, 256>>>(A, XNb);
    gemm_cos_sk<<<272, 256, SMEM_SQ>>>(XNb, T, S);                        // cos partials
    cosred_trans_kernel<<<GRT, 256>>>(T, S, Mb, A, ATb);                  // Mb + x^T
    gemm_big<0><<<gbig, 256, SMEM_BIG>>>(Mb, ATb, T, nullptr, nullptr);   // mat @ x
    softmax_kernel<<<NR, 256>>>(T, Tb);
    gemm_big<2><<<gbig, 256, SMEM_BIG>>>(Tb, Wtb, B, bt, A);              // x2

    // ---- layer 2 ----
    normalize_kernel<<<NR, 256>>>(B, XNb);
    gemm_cos_sk<<<272, 256, SMEM_SQ>>>(XNb, T, S);
    cosred_trans_kernel<<<GRT, 256>>>(T, S, Mb, B, ATb);
    gemm_big<0><<<gbig, 256, SMEM_BIG>>>(Mb, ATb, T, nullptr, nullptr);
    softmax_kernel<<<NR, 256>>>(T, Tb);
    gemm_big<2><<<gbig, 256, SMEM_BIG>>>(Tb, Wrb, A, br, B);              // x3

    // ---- heads (partials into T scratch) ----
    head_partial<<<dim3(64, 8), 256>>>(A, Wc, Wb, T);
    head_reduce<<<(NR * 45 + 255) / 256, 256>>>(T, bc, bb, out);
}

// round 17
// speedup vs baseline: 1.4125x; 1.4125x over previous
#include <cuda_runtime.h>
#include <cuda_bf16.h>
#include <math.h>
#include <stddef.h>
#include <stdint.h>

#define NR 2048
#define DD 2048
#define NCLS 9
#define NBB 36

// ---- scratch (device globals: allocation-free rule) ----
__device__ float g_A[NR * DD];                 // feat / x3 (fp32, residual)
__device__ float g_B[NR * DD];                 // x2 (fp32, residual)
__device__ float g_T[NR * DD];                 // mat@x fp32; cos partial S0; head partials
__device__ float g_S[NR * NR];                 // cos partial S1
__device__ __nv_bfloat16 g_XNb[NR * DD];       // normalized feats (bf16)
__device__ __nv_bfloat16 g_Mb[NR * NR];        // cosine matrix (bf16)
__device__ __nv_bfloat16 g_ATb[NR * DD];       // x^T (bf16)
__device__ __nv_bfloat16 g_Tb[NR * DD];        // softmax(mat@x) (bf16)
__device__ __nv_bfloat16 g_Wtb[DD * DD];       // Wt (bf16)
__device__ __nv_bfloat16 g_Wrb[DD * DD];       // Wr (bf16)

// =====================================================================
// helpers
// =====================================================================
__device__ __forceinline__ uint32_t smem_u32(const void* p) {
    uint32_t a;
    asm("{ .reg .u64 t; cvta.to.shared.u64 t, %1; cvt.u32.u64 %0, t; }"
        : "=r"(a) : "l"(p));
    return a;
}
__device__ __forceinline__ uint32_t pack2(float lo, float hi) {
    uint32_t r;
    asm("cvt.rn.bf16x2.f32 %0, %1, %2;" : "=r"(r) : "f"(hi), "f"(lo));
    return r;
}
#define CP_ASYNC16(dst, src) \
    asm volatile("cp.async.ca.shared.global [%0], [%1], 16;" :: "r"(dst), "l"(src) : "memory")
#define CP_COMMIT() asm volatile("cp.async.commit_group;" ::: "memory")
#define CP_WAIT(n)  asm volatile("cp.async.wait_group %0;" :: "n"(n) : "memory")
#define LDMATRIX_X4(r, addr)                                              \
    asm volatile("ldmatrix.sync.aligned.m8n8.x4.shared.b16 "              \
                 "{%0,%1,%2,%3}, [%4];"                                   \
                 : "=r"((r)[0]), "=r"((r)[1]), "=r"((r)[2]), "=r"((r)[3]) \
                 : "r"(addr))

__device__ __forceinline__ void mma_bf16(float* c, const uint32_t* a, const uint32_t* b) {
    asm volatile(
        "mma.sync.aligned.m16n8k16.row.col.f32.bf16.bf16.f32 "
        "{%0,%1,%2,%3}, {%4,%5,%6,%7}, {%8,%9}, {%0,%1,%2,%3};"
        : "+f"(c[0]), "+f"(c[1]), "+f"(c[2]), "+f"(c[3])
        : "r"(a[0]), "r"(a[1]), "r"(a[2]), "r"(a[3]), "r"(b[0]), "r"(b[1]));
}

// =====================================================================
// AvgPool + f2b (block-range dispatch)
// =====================================================================
__global__ void avgpool_f2b_kernel(const float* __restrict__ x, float* __restrict__ out,
                                   const float* __restrict__ Wt, const float* __restrict__ Wr,
                                   __nv_bfloat16* __restrict__ Wtb,
                                   __nv_bfloat16* __restrict__ Wrb) {
    __shared__ float s[128 * 49];
    const int b = blockIdx.x;
    if (b < 32768) {
        size_t block0 = (size_t)b * 128;
        const float4* src = reinterpret_cast<const float4*>(x + block0 * 49);
        float4* dst = reinterpret_cast<float4*>(s);
        for (int i = threadIdx.x; i < 128 * 49 / 4; i += 256) dst[i] = src[i];
        __syncthreads();
        if (threadIdx.x < 128) {
            float sum = 0.f;
            #pragma unroll
            for (int k = 0; k < 49; k++) sum += s[threadIdx.x * 49 + k];
            out[block0 + threadIdx.x] = sum * (1.f / 49.f);
        }
    } else {
        const int fb = b - 32768;
        const float* in = (fb < 2048) ? Wt : Wr;
        __nv_bfloat16* o8 = (fb < 2048) ? Wtb : Wrb;
        size_t i = ((size_t)(fb & 2047) * 256 + threadIdx.x) * 8;
        const float4 a = *(const float4*)(in + i);
        const float4 c = *(const float4*)(in + i + 4);
        uint4 o;
        o.x = pack2(a.x, a.y); o.y = pack2(a.z, a.w);
        o.z = pack2(c.x, c.y); o.w = pack2(c.z, c.w);
        *(uint4*)(o8 + i) = o;
    }
}

// =====================================================================
// Row L2-normalize -> bf16 (shuffle reduction, 1 barrier)
// =====================================================================
__global__ void normalize_kernel(const float* __restrict__ f, __nv_bfloat16* __restrict__ fn) {
    __shared__ float wsum[8];
    const int row = blockIdx.x, t = threadIdx.x;
    const int lane = t & 31, w = t >> 5;
    const float4* p = reinterpret_cast<const float4*>(f + (size_t)row * DD);
    float4 v0 = p[2 * t], v1 = p[2 * t + 1];
    float s = v0.x * v0.x + v0.y * v0.y + v0.z * v0.z + v0.w * v0.w
            + v1.x * v1.x + v1.y * v1.y + v1.z * v1.z + v1.w * v1.w;
    #pragma unroll
    for (int o = 16; o; o >>= 1) s += __shfl_xor_sync(0xffffffffu, s, o);
    if (lane == 0) wsum[w] = s;
    __syncthreads();
    s = wsum[0];
    #pragma unroll
    for (int i = 1; i < 8; i++) s += wsum[i];
    const float inv = 1.f / fmaxf(sqrtf(s), 1e-8f);
    uint4 o;
    o.x = pack2(v0.x * inv, v0.y * inv);
    o.y = pack2(v0.z * inv, v0.w * inv);
    o.z = pack2(v1.x * inv, v1.y * inv);
    o.w = pack2(v1.z * inv, v1.w * inv);
    *(uint4*)(fn + (size_t)row * DD + t * 8) = o;
}

// =====================================================================
// Row softmax: fp32 in -> bf16 out (shuffle reductions, 2 barriers)
// =====================================================================
__global__ void softmax_kernel(const float* __restrict__ in, __nv_bfloat16* __restrict__ outb) {
    __shared__ float wmax[8];
    __shared__ float wsum[8];
    const int row = blockIdx.x, t = threadIdx.x;
    const int lane = t & 31, w = t >> 5;
    const float4* p = reinterpret_cast<const float4*>(in + (size_t)row * NR);
    float4 u0 = p[2 * t], u1 = p[2 * t + 1];
    float v[8] = {u0.x, u0.y, u0.z, u0.w, u1.x, u1.y, u1.z, u1.w};
    float mx = v[0];
    #pragma unroll
    for (int i = 1; i < 8; i++) mx = fmaxf(mx, v[i]);
    #pragma unroll
    for (int o = 16; o; o >>= 1) mx = fmaxf(mx, __shfl_xor_sync(0xffffffffu, mx, o));
    if (lane == 0) wmax[w] = mx;
    __syncthreads();
    mx = wmax[0];
    #pragma unroll
    for (int i = 1; i < 8; i++) mx = fmaxf(mx, wmax[i]);

    float s = 0.f;
    #pragma unroll
    for (int i = 0; i < 8; i++) {
        v[i] = __expf(v[i] - mx);
        s += v[i];
    }
    #pragma unroll
    for (int o = 16; o; o >>= 1) s += __shfl_xor_sync(0xffffffffu, s, o);
    if (lane == 0) wsum[w] = s;
    __syncthreads();
    s = wsum[0];
    #pragma unroll
    for (int i = 1; i < 8; i++) s += wsum[i];

    const float inv = 1.f / s;
    uint4 o;
    o.x = pack2(v[0] * inv, v[1] * inv);
    o.y = pack2(v[2] * inv, v[3] * inv);
    o.z = pack2(v[4] * inv, v[5] * inv);
    o.w = pack2(v[6] * inv, v[7] * inv);
    *(uint4*)(outb + (size_t)row * NR + t * 8) = o;
}

// =====================================================================
// Cosine GEMM split-K: 128x128 tile, K split into 2 halves of 1024.
// grid = 272: tile = bx>>1, half = bx&1. fp32 partial -> S0/S1.
// =====================================================================
#define STG 16384

__device__ __forceinline__ void load_stage_sq(uint32_t sb32,
                                              const __nv_bfloat16* A, const __nv_bfloat16* B,
                                              int bm0, int bn0, int k0, int buf, int t) {
    const int ch = t & 7;
    const int r0 = t >> 3;
    const uint32_t abase = sb32 + (uint32_t)buf * (2 * STG);
    #pragma unroll
    for (int p = 0; p < 4; p++) {
        const int row = r0 + p * 32;
        uint32_t o = (uint32_t)row * 128 + ch * 16;
        uint32_t sw = o ^ ((o >> 3) & 0x70);
        CP_ASYNC16(abase + sw, A + (size_t)(bm0 + row) * DD + k0 + ch * 8);
        CP_ASYNC16(abase + STG + sw, B + (size_t)(bn0 + row) * DD + k0 + ch * 8);
    }
}

__global__ __launch_bounds__(256, 2)
void gemm_cos_sk(const __nv_bfloat16* __restrict__ XN,
                 float* __restrict__ S0, float* __restrict__ S1) {
    extern __shared__ char dynsm[];
    char* sb = (char*)(((uintptr_t)dynsm + 1023) & ~(uintptr_t)1023);
    const uint32_t sb32 = smem_u32(sb);
    const int t = threadIdx.x;
    const int lane = t & 31, wid = t >> 5;
    const int wm = (wid & 3) * 32;
    const int wn = (wid >> 2) * 64;

    const int half = blockIdx.x & 1;
    int rem = blockIdx.x >> 1, i = 0;
    while (rem >= 16 - i) { rem -= 16 - i; i++; }
    const int bm0 = i * 128;
    const int bn0 = (i + rem) * 128;
    const int kbase = half * 1024;
    float* S = half ? S1 : S0;

    float acc[2][8][4];
    #pragma unroll
    for (int a = 0; a < 2; a++)
        #pragma unroll
        for (int b = 0; b < 8; b++)
            #pragma unroll
            for (int q = 0; q < 4; q++) acc[a][b][q] = 0.f;

    load_stage_sq(sb32, XN, XN, bm0, bn0, kbase, 0, t);
    CP_COMMIT();

    const int a_row_l = lane & 15;
    const int a_kb = (lane >> 4) * 16;
    const int b_row_l = ((lane >> 4) << 3) + (lane & 7);
    const int b_kb = ((lane >> 3) & 1) * 16;

    for (int s = 0; s < 16; s++) {
        if (s < 15) {
            load_stage_sq(sb32, XN, XN, bm0, bn0, kbase + (s + 1) * 64, (s + 1) & 1, t);
            CP_COMMIT();
            CP_WAIT(1);
        } else {
            CP_WAIT(0);
        }
        __syncthreads();
        const uint32_t aB = sb32 + (uint32_t)(s & 1) * (2 * STG);
        const uint32_t bB = aB + STG;
        #pragma unroll
        for (int kk = 0; kk < 4; kk++) {
            const int kb = kk * 32;
            uint32_t af[2][4], bf[4][4];
            #pragma unroll
            for (int mt = 0; mt < 2; mt++) {
                uint32_t o = (uint32_t)(wm + mt * 16 + a_row_l) * 128 + kb + a_kb;
                LDMATRIX_X4(af[mt], aB + (o ^ ((o >> 3) & 0x70)));
            }
            #pragma unroll
            for (int nt2 = 0; nt2 < 4; nt2++) {
                uint32_t o = (uint32_t)(wn + nt2 * 16 + b_row_l) * 128 + kb + b_kb;
                LDMATRIX_X4(bf[nt2], bB + (o ^ ((o >> 3) & 0x70)));
            }
            #pragma unroll
            for (int mt = 0; mt < 2; mt++)
                #pragma unroll
                for (int nt2 = 0; nt2 < 4; nt2++) {
                    mma_bf16(acc[mt][nt2 * 2 + 0], af[mt], &bf[nt2][0]);
                    mma_bf16(acc[mt][nt2 * 2 + 1], af[mt], &bf[nt2][2]);
                }
        }
        __syncthreads();
    }

    const int g = lane >> 2;
    const int c2 = (lane & 3) * 2;
    #pragma unroll
    for (int mt = 0; mt < 2; mt++) {
        const int row0 = bm0 + wm + mt * 16 + g;
        #pragma unroll
        for (int nt = 0; nt < 8; nt++) {
            const int col0 = bn0 + wn + nt * 8 + c2;
            float2 o0 = {acc[mt][nt][0], acc[mt][nt][1]};
            float2 o1 = {acc[mt][nt][2], acc[mt][nt][3]};
            *(float2*)&S[(size_t)row0 * NR + col0] = o0;
            *(float2*)&S[(size_t)(row0 + 8) * NR + col0] = o1;
        }
    }
}

// =====================================================================
// FUSED cosred + transpose (block-range dispatch; both branches keep
// their per-block structure and share the static smem tile):
//  [0, 2176)        : cosred 32x32 sub-tile (Mb = bf16(S0+S1) + mirror)
//  [2176, +4096)    : 32x32 transpose tile Afp^T -> AT (bf16)
// =====================================================================
__global__ __launch_bounds__(256)
void cosred_trans_kernel(const float* __restrict__ S0, const float* __restrict__ S1,
                         __nv_bfloat16* __restrict__ C,
                         const float* __restrict__ Afp, __nv_bfloat16* __restrict__ AT) {
    __shared__ float tile[32][33];
    const int b = blockIdx.x;
    const int tx = threadIdx.x & 31, ty = threadIdx.x >> 5;

    if (b < 2176) {
        // ---- cosred branch ----
        const int tix = b >> 4, sub = b & 15;
        int rem = tix, i = 0;
        while (rem >= 16 - i) { rem -= 16 - i; i++; }
        const int bm0 = i * 128;
        const int bn0 = (i + rem) * 128;
        const int sr = bm0 + (sub >> 2) * 32;
        const int sc = bn0 + (sub & 3) * 32;

        #pragma unroll
        for (int j = 0; j < 32; j += 8) {
            const int r = sr + ty + j;
            const size_t idx = (size_t)r * NR + sc + tx;
            float v = S0[idx] + S1[idx];
            C[idx] = __float2bfloat16_rn(v);
            tile[ty + j][tx] = v;
        }
        if (bm0 != bn0) {
            __syncthreads();
            #pragma unroll
            for (int j = 0; j < 32; j += 8) {
                const int r = sc + ty + j;
                C[(size_t)r * NR + sr + tx] = __float2bfloat16_rn(tile[tx][ty + j]);
            }
        }
    } else {
        // ---- transpose branch ----
        const int idx = b - 2176;
        const int bx = idx & 63, by = idx >> 6;
        int x = bx * 32 + tx;
        int y = by * 32 + ty;
        #pragma unroll
        for (int j = 0; j < 32; j += 8)
            tile[ty + j][tx] = Afp[(size_t)(y + j) * DD + x];
        __syncthreads();
        x = by * 32 + tx;
        y = bx * 32 + ty;
        #pragma unroll
        for (int j = 0; j < 32; j += 8)
            AT[(size_t)(y + j) * DD + x] = __float2bfloat16_rn(tile[tx][ty + j]);
    }
}

// =====================================================================
// BIG bf16 NT GEMM: 256x128 CTA tile, 8 warps @ 64x64, BK=64, 3-stage.
// EPI: 0 plain fp32 | 2 (+bias[c]+res[r,c]) fp32.
// =====================================================================
#define BSTG 49152
#define NSTAGE 3

__device__ __forceinline__ void load_stage_big(uint32_t sb32,
                                               const __nv_bfloat16* A, const __nv_bfloat16* B,
                                               int bm0, int bn0, int k0, int buf, int t) {
    const int ch = t & 7;
    const int r0 = t >> 3;
    const uint32_t base = sb32 + (uint32_t)buf * BSTG;
    #pragma unroll
    for (int p = 0; p < 8; p++) {
        const int row = r0 + p * 32;
        uint32_t o = (uint32_t)row * 128 + ch * 16;
        CP_ASYNC16(base + (o ^ ((o >> 3) & 0x70)),
                   A + (size_t)(bm0 + row) * DD + k0 + ch * 8);
    }
    #pragma unroll
    for (int p = 0; p < 4; p++) {
        const int row = r0 + p * 32;
        uint32_t o = (uint32_t)row * 128 + ch * 16;
        CP_ASYNC16(base + 32768u + (o ^ ((o >> 3) & 0x70)),
                   B + (size_t)(bn0 + row) * DD + k0 + ch * 8);
    }
}

template <int EPI>
__global__ __launch_bounds__(256, 1)
void gemm_big(const __nv_bfloat16* __restrict__ A, const __nv_bfloat16* __restrict__ B,
              float* __restrict__ C,
              const float* __restrict__ bias,
              const float* __restrict__ res) {
    extern __shared__ char dynsm[];
    char* sb = (char*)(((uintptr_t)dynsm + 1023) & ~(uintptr_t)1023);
    const uint32_t sb32 = smem_u32(sb);

    const int t = threadIdx.x;
    const int lane = t & 31, wid = t >> 5;
    const int wm = (wid & 3) * 64;
    const int wn = (wid >> 2) * 64;
    const int bm0 = blockIdx.y * 256;
    const int bn0 = blockIdx.x * 128;

    float acc[4][8][4];
    #pragma unroll
    for (int i = 0; i < 4; i++)
        #pragma unroll
        for (int j = 0; j < 8; j++)
            #pragma unroll
            for (int q = 0; q < 4; q++) acc[i][j][q] = 0.f;

    load_stage_big(sb32, A, B, bm0, bn0, 0, 0, t);
    CP_COMMIT();
    load_stage_big(sb32, A, B, bm0, bn0, 64, 1, t);
    CP_COMMIT();

    const int a_row_l = lane & 15;
    const int a_kb = (lane >> 4) * 16;
    const int b_row_l = ((lane >> 4) << 3) + (lane & 7);
    const int b_kb = ((lane >> 3) & 1) * 16;

    int buf = 0;
    for (int s = 0; s < 32; s++) {
        if (s < 31) { CP_WAIT(1); } else { CP_WAIT(0); }
        __syncthreads();
        if (s < 30) {
            int nb = buf + 2; if (nb >= NSTAGE) nb -= NSTAGE;
            load_stage_big(sb32, A, B, bm0, bn0, (s + 2) * 64, nb, t);
            CP_COMMIT();
        }

        const uint32_t aB = sb32 + (uint32_t)buf * BSTG;
        const uint32_t bB = aB + 32768u;
        #pragma unroll
        for (int kk = 0; kk < 4; kk++) {
            const int kb = kk * 32;
            uint32_t af[4][4], bf[4][4];
            #pragma unroll
            for (int mt = 0; mt < 4; mt++) {
                uint32_t o = (uint32_t)(wm + mt * 16 + a_row_l) * 128 + kb + a_kb;
                LDMATRIX_X4(af[mt], aB + (o ^ ((o >> 3) & 0x70)));
            }
            #pragma unroll
            for (int nt2 = 0; nt2 < 4; nt2++) {
                uint32_t o = (uint32_t)(wn + nt2 * 16 + b_row_l) * 128 + kb + b_kb;
                LDMATRIX_X4(bf[nt2], bB + (o ^ ((o >> 3) & 0x70)));
            }
            #pragma unroll
            for (int mt = 0; mt < 4; mt++)
                #pragma unroll
                for (int nt2 = 0; nt2 < 4; nt2++) {
                    mma_bf16(acc[mt][nt2 * 2 + 0], af[mt], &bf[nt2][0]);
                    mma_bf16(acc[mt][nt2 * 2 + 1], af[mt], &bf[nt2][2]);
                }
        }
        if (++buf == NSTAGE) buf = 0;
    }

    const int g = lane >> 2;
    const int c2 = (lane & 3) * 2;
    #pragma unroll
    for (int mt = 0; mt < 4; mt++) {
        const int row0 = bm0 + wm + mt * 16 + g;
        #pragma unroll
        for (int nt = 0; nt < 8; nt++) {
            const int col0 = bn0 + wn + nt * 8 + c2;
            float v0 = acc[mt][nt][0], v1 = acc[mt][nt][1];
            float v2 = acc[mt][nt][2], v3 = acc[mt][nt][3];
            if (EPI == 2) {
                float b0 = bias[col0], b1 = bias[col0 + 1];
                const float2 r0 = *(const float2*)&res[(size_t)row0 * DD + col0];
                const float2 r1 = *(const float2*)&res[(size_t)(row0 + 8) * DD + col0];
                v0 += b0 + r0.x; v1 += b1 + r0.y;
                v2 += b0 + r1.x; v3 += b1 + r1.y;
            }
            float2 o0 = {v0, v1}, o1 = {v2, v3};
            *(float2*)&C[(size_t)row0 * DD + col0] = o0;
            *(float2*)&C[(size_t)(row0 + 8) * DD + col0] = o1;
        }
    }
}

// =====================================================================
// Head, split-K (k-step-4 inner loop: float4 W broadcasts)
// =====================================================================
__global__ __launch_bounds__(256)
void head_partial(const float* __restrict__ x,
                  const float* __restrict__ Wc, const float* __restrict__ Wb,
                  float* __restrict__ part) {
    __shared__ float Wsm[48 * 64];
    __shared__ float xs[32 * 65];
    const int rb = blockIdx.x, ks = blockIdx.y;
    const int t = threadIdx.x;
    const int r = t & 31, jg = t >> 5;

    float acc[6] = {0.f, 0.f, 0.f, 0.f, 0.f, 0.f};

    for (int k0 = ks * 256; k0 < ks * 256 + 256; k0 += 64) {
        for (int i = t; i < 48 * 64; i += 256) {
            int j = i >> 6, k = i & 63;
            if (j < 45) {
                const float* w = (j < NCLS) ? (Wc + (size_t)j * DD)
                                            : (Wb + (size_t)(j - NCLS) * DD);
                Wsm[i] = w[k0 + k];
            } else {
                Wsm[i] = 0.f;
            }
        }
        for (int i = t; i < 32 * 64; i += 256) {
            int rr = i >> 6, k = i & 63;
            xs[rr * 65 + k] = x[(size_t)(rb * 32 + rr) * DD + k0 + k];
        }
        __syncthreads();
        #pragma unroll 4
        for (int k = 0; k < 64; k += 4) {
            float xv0 = xs[r * 65 + k + 0];
            float xv1 = xs[r * 65 + k + 1];
            float xv2 = xs[r * 65 + k + 2];
            float xv3 = xs[r * 65 + k + 3];
            #pragma unroll
            for (int u = 0; u < 6; u++) {
                const int j = jg + 8 * u;
                const float4 w = *(const float4*)&Wsm[j * 64 + k];
                acc[u] += xv0 * w.x + xv1 * w.y + xv2 * w.z + xv3 * w.w;
            }
        }
        __syncthreads();
    }
    #pragma unroll
    for (int u = 0; u < 6; u++) {
        int j = jg + 8 * u;
        if (j < 45)
            part[((size_t)ks * NR + rb * 32 + r) * 45 + j] = acc[u];
    }
}

__global__ void head_reduce(const float* __restrict__ part,
                            const float* __restrict__ bc, const float* __restrict__ bb,
                            float* __restrict__ out) {
    int idx = blockIdx.x * 256 + threadIdx.x;
    if (idx >= NR * 45) return;
    int i = idx / 45, j = idx - i * 45;
    float s = 0.f;
    #pragma unroll
    for (int ks = 0; ks < 8; ks++) s += part[((size_t)ks * NR + i) * 45 + j];
    if (j < NCLS)
        out[(size_t)i * NCLS + j] = s + bc[j];
    else
        out[(size_t)NR * NCLS + (size_t)i * NBB + (j - NCLS)] = s + bb[j - NCLS];
}

// =====================================================================
extern "C" void kernel_launch(void* const* d_in, const int* in_sizes, int n_in,
                              void* d_out, int out_size) {
    const float* x  = (const float*)d_in[0];
    const float* Wt = (const float*)d_in[1];
    const float* bt = (const float*)d_in[2];
    const float* Wr = (const float*)d_in[3];
    const float* br = (const float*)d_in[4];
    const float* Wc = (const float*)d_in[5];
    const float* bc = (const float*)d_in[6];
    const float* Wb = (const float*)d_in[7];
    const float* bb = (const float*)d_in[8];
    float* out = (float*)d_out;

    float *A, *B, *T, *S;
    __nv_bfloat16 *XNb, *Mb, *ATb, *Tb, *Wtb, *Wrb;
    cudaGetSymbolAddress((void**)&A, g_A);
    cudaGetSymbolAddress((void**)&B, g_B);
    cudaGetSymbolAddress((void**)&T, g_T);
    cudaGetSymbolAddress((void**)&S, g_S);
    cudaGetSymbolAddress((void**)&XNb, g_XNb);
    cudaGetSymbolAddress((void**)&Mb, g_Mb);
    cudaGetSymbolAddress((void**)&ATb, g_ATb);
    cudaGetSymbolAddress((void**)&Tb, g_Tb);
    cudaGetSymbolAddress((void**)&Wtb, g_Wtb);
    cudaGetSymbolAddress((void**)&Wrb, g_Wrb);

    const int SMEM_SQ  = 4 * STG + 1024;          // 66560 B
    const int SMEM_BIG = NSTAGE * BSTG + 1024;    // 148480 B
    cudaFuncSetAttribute(gemm_cos_sk, cudaFuncAttributeMaxDynamicSharedMemorySize, SMEM_SQ);
    cudaFuncSetAttribute(gemm_big<0>, cudaFuncAttributeMaxDynamicSharedMemorySize, SMEM_BIG);
    cudaFuncSetAttribute(gemm_big<2>, cudaFuncAttributeMaxDynamicSharedMemorySize, SMEM_BIG);

    dim3 gbig(16, 8);
    const int GRT = 2176 + 4096;   // cosred sub-tiles + transpose tiles

    // avgpool + both weight converts in one launch
    avgpool_f2b_kernel<<<32768 + 4096, 256>>>(x, A, Wt, Wr, Wtb, Wrb);

    // ---- layer 1 ----
    normalize_kernel<<<NR, 256>>>(A, XNb);
    gemm_cos_sk<<<272, 256, SMEM_SQ>>>(XNb, T, S);                        // cos partials
    cosred_trans_kernel<<<GRT, 256>>>(T, S, Mb, A, ATb);                  // Mb + x^T
    gemm_big<0><<<gbig, 256, SMEM_BIG>>>(Mb, ATb, T, nullptr, nullptr);   // mat @ x
    softmax_kernel<<<NR, 256>>>(T, Tb);
    gemm_big<2><<<gbig, 256, SMEM_BIG>>>(Tb, Wtb, B, bt, A);              // x2

    // ---- layer 2 ----
    normalize_kernel<<<NR, 256>>>(B, XNb);
    gemm_cos_sk<<<272, 256, SMEM_SQ>>>(XNb, T, S);
    cosred_trans_kernel<<<GRT, 256>>>(T, S, Mb, B, ATb);
    gemm_big<0><<<gbig, 256, SMEM_BIG>>>(Mb, ATb, T, nullptr, nullptr);
    softmax_kernel<<<NR, 256>>>(T, Tb);
    gemm_big<2><<<gbig, 256, SMEM_BIG>>>(Tb, Wrb, A, br, B);              // x3

    // ---- heads (partials into T scratch) ----
    head_partial<<<dim3(64, 8), 256>>>(A, Wc, Wb, T);
    head_reduce<<<(NR * 45 + 255) / 256, 256>>>(T, bc, bb, out);
}